// round 5
// baseline (speedup 1.0000x reference)
#include <cuda_runtime.h>
#include <cuda_fp16.h>
#include <cstdint>

// Problem constants (fixed by the dataset)
#define NC   1000      // cells
#define NGOI 500       // genes of interest
#define NGT  5000      // total genes
#define NL   10        // latent dim
#define NK   129       // knots (NBINS+1)
#define NPAIR (NC*NGOI)

#define MAIN_BLOCKS 1184
#define MAIN_THREADS 256
#define CSPLIT 8              // cell splits in k_delta
#define CPB (NC / CSPLIT)     // 125 cells per block

// ---------------- device scratch (static: no allocation allowed) -------------
__device__ float  g_logits[NC * NGT];                 // 20 MB raw logits
__device__ float  g_lse[NC];
__device__ __half g_E[(size_t)NPAIR * 128];           // 128 MB exp(delta), knots 0..127
__device__ __half g_E128[NPAIR];                      // 1 MB   exp(delta) knot 128
__device__ __half g_B[NGOI * 128];                    // 128 KB exp(baseline), knots 0..127
__device__ __half g_B128[NGOI];                       //        exp(baseline) knot 128
__device__ double g_part[MAIN_BLOCKS];

// ---------------- kernel: overall logits [NC x NGT] --------------------------
__global__ void k_logits(const float* __restrict__ latent,
                         const float* __restrict__ wo,
                         const float* __restrict__ ob) {
    __shared__ float lat[16 * NL];
    int g  = blockIdx.x * 256 + threadIdx.x;
    int c0 = blockIdx.y * 16;
    int t = threadIdx.x;
    if (t < 16 * NL) {
        int cc = c0 + t / NL;
        lat[t] = (cc < NC) ? latent[cc * NL + t % NL] : 0.f;
    }
    __syncthreads();
    if (g >= NGT) return;
    float w[NL];
#pragma unroll
    for (int l = 0; l < NL; l++) w[l] = wo[g * NL + l];
    float base = ob[g];
    int cmax = NC - c0; if (cmax > 16) cmax = 16;
    for (int c = 0; c < cmax; c++) {
        float a = base;
#pragma unroll
        for (int l = 0; l < NL; l++) a = fmaf(lat[c * NL + l], w[l], a);
        g_logits[(c0 + c) * NGT + g] = a;
    }
}

// ---------------- kernel: per-cell log-sum-exp (read-only, vectorized) -------
__global__ void k_lse() {
    int c = blockIdx.x;
    const float4* row = (const float4*)&g_logits[c * NGT];  // 1250 float4
    float s = 0.f;
    for (int i = threadIdx.x; i < NGT / 4; i += 512) {
        float4 v = row[i];
        s += __expf(v.x) + __expf(v.y) + __expf(v.z) + __expf(v.w);
    }
    __shared__ float sh[16];
#pragma unroll
    for (int o = 16; o; o >>= 1) s += __shfl_xor_sync(0xffffffffu, s, o);
    if ((threadIdx.x & 31) == 0) sh[threadIdx.x >> 5] = s;
    __syncthreads();
    if (threadIdx.x < 16) {
        s = sh[threadIdx.x];
#pragma unroll
        for (int o = 8; o; o >>= 1) s += __shfl_xor_sync(0xffffu, s, o);
        if (threadIdx.x == 0) g_lse[c] = __logf(s);
    }
}

// ---------------- kernel: baseline exp table --------------------------------
__global__ void k_bexp(const float* __restrict__ sb, const int* __restrict__ goi) {
    int j = blockIdx.x;
    int gene = goi[j];
    int t = threadIdx.x;
    if (t < NK) {
        __half v = __float2half_rn(__expf(sb[(size_t)gene * NK + t]));
        if (t < 128) g_B[j * 128 + t] = v;
        else         g_B128[j] = v;
    }
}

// ---------------- kernel: exp(delta) knot 128 per pair ------------------------
__global__ void k_e128(const float* __restrict__ latent,
                       const float* __restrict__ hw,
                       const int*   __restrict__ goi) {
    __shared__ float W4[NL];
    int j = blockIdx.x;
    int gene = goi[j];
    if (threadIdx.x < NL)
        W4[threadIdx.x] = hw[(size_t)gene * NL * NK + threadIdx.x * NK + 128];
    __syncthreads();
    for (int c = threadIdx.x; c < NC; c += 256) {
        float a = 0.f;
#pragma unroll
        for (int l = 0; l < NL; l++) a = fmaf(latent[c * NL + l], W4[l], a);
        g_E128[c * NGOI + j] = __float2half_rn(__expf(a));
    }
}

// ---------------- kernel: exp(delta) table, knots 0..127 ----------------------
// E[c*NGOI+j][k] = exp( sum_l latent[c][l] * hw[goi[j]][l][k] )
__global__ void __launch_bounds__(256, 4) k_delta(const float* __restrict__ latent,
                                                  const float* __restrict__ hw,
                                                  const int*   __restrict__ goi) {
    __shared__ float slat[CPB * 12];        // latent slice, stride 12
    int j = blockIdx.x;
    int gene = goi[j];
    int c0 = blockIdx.y * CPB;
    int tid = threadIdx.x;
    int w = tid >> 5, lane = tid & 31;

    for (int i = tid; i < CPB * NL; i += 256) {
        int cc = i / NL, l = i - cc * NL;
        slat[cc * 12 + l] = latent[(c0 + cc) * NL + l];
    }

    // per-lane knots: k4..k4+3
    int k4 = lane * 4;
    const float* wp = hw + (size_t)gene * NL * NK;
    float W0[NL], W1[NL], W2[NL], W3[NL];
#pragma unroll
    for (int l = 0; l < NL; l++) {
        const float* r = wp + l * NK;
        W0[l] = r[k4];     W1[l] = r[k4 + 1];
        W2[l] = r[k4 + 2]; W3[l] = r[k4 + 3];
    }
    __syncthreads();

    const float* sp = &slat[w * 12];
    __half* ep = g_E + ((size_t)(c0 + w) * NGOI + j) * 128 + k4;
    for (int c = w; c < CPB; c += 8, sp += 8 * 12, ep += (size_t)8 * NGOI * 128) {
        const float4 la = *(const float4*)sp;
        const float4 lb = *(const float4*)(sp + 4);
        const float2 lc = *(const float2*)(sp + 8);
        float lv[NL] = {la.x, la.y, la.z, la.w, lb.x, lb.y, lb.z, lb.w, lc.x, lc.y};
        float a0 = 0.f, a1 = 0.f, a2 = 0.f, a3 = 0.f;
#pragma unroll
        for (int l = 0; l < NL; l++) {
            a0 = fmaf(lv[l], W0[l], a0);
            a1 = fmaf(lv[l], W1[l], a1);
            a2 = fmaf(lv[l], W2[l], a2);
            a3 = fmaf(lv[l], W3[l], a3);
        }
        __half2 h01 = __floats2half2_rn(__expf(a0), __expf(a1));
        __half2 h23 = __floats2half2_rn(__expf(a2), __expf(a3));
        uint2 st;
        st.x = *(const unsigned*)&h01;
        st.y = *(const unsigned*)&h23;
        *(uint2*)ep = st;
    }
}

// ---------------- kernel: per-cut spline log-prob, warp per cut ---------------
__global__ void __launch_bounds__(MAIN_THREADS) k_main(
        const float* __restrict__ coord,
        const int*   __restrict__ cxg,    // pair index p
        const int*   __restrict__ lcxg,   // cell x total-gene index q
        const int*   __restrict__ gloc,   // local gene index gl
        int ncuts) {
    int w = threadIdx.x >> 5, lane = threadIdx.x & 31;
    int gw = blockIdx.x * (MAIN_THREADS >> 5) + w;
    int nw = gridDim.x * (MAIN_THREADS >> 5);
    int k4 = lane * 4;
    double acc = 0.0;
    const float C = 4.852030263919617f + 8.517193191416238f; // ln(128)+ln(5000)
    const unsigned FULL = 0xffffffffu;

    for (int i = gw; i < ncuts; i += nw) {
        int   p  = __ldg(&cxg[i]);
        int   gl = __ldg(&gloc[i]);
        float x  = __ldg(&coord[i]);

        uint2 er = *(const uint2*)&g_E[(size_t)p * 128 + k4];
        uint2 br = *(const uint2*)&g_B[gl * 128 + k4];
        float2 e01 = __half22float2(*(const __half2*)&er.x);
        float2 e23 = __half22float2(*(const __half2*)&er.y);
        float2 b01 = __half22float2(*(const __half2*)&br.x);
        float2 b23 = __half22float2(*(const __half2*)&br.y);
        float u0 = e01.x * b01.x;
        float u1 = e01.y * b01.y;
        float u2 = e23.x * b23.x;
        float u3 = e23.y * b23.y;

        float s = u0 + u1 + u2 + u3;
        float u128 = 0.f;
        if (lane == 31) {
            u128 = __half2float(g_E128[p]) * __half2float(g_B128[gl]);
            s += 0.5f * u128;                 // top endpoint (half weight)
        }
        if (lane == 0) s -= 0.5f * u0;        // halve bottom endpoint

        float xs = fminf(fmaxf(x, 0.f), 0.999999f) * 128.f;
        int bi = (int)xs; if (bi > 127) bi = 127;
        float alpha = xs - (float)bi;

        int lb = bi >> 2, cb = bi & 3;
        int rk = bi + 1;
        int lr = (rk == 128) ? 31 : (rk >> 2);
        int cr = rk & 3;
        float selL = (cb == 0) ? u0 : (cb == 1) ? u1 : (cb == 2) ? u2 : u3;
        float selR = (cr == 0) ? u0 : (cr == 1) ? u1 : (cr == 2) ? u2 : u3;
        if (rk == 128) selR = u128;
        float L = __shfl_sync(FULL, selL, lb);
        float R = __shfl_sync(FULL, selR, lr);

#pragma unroll
        for (int o = 16; o; o >>= 1) s += __shfl_xor_sync(FULL, s, o);

        if (lane == 0) {
            int q = __ldg(&lcxg[i]);
            unsigned cell = (unsigned)q / (unsigned)NGT;
            float nl = __ldg(&g_logits[q]) - g_lse[cell];
            float val = __logf(fmaf(alpha, R - L, L)) - __logf(s) + C + nl;
            acc += (double)val;
        }
    }

    __shared__ double sh[MAIN_THREADS / 32];
    if (lane == 0) sh[w] = acc;
    __syncthreads();
    if (threadIdx.x == 0) {
        double t = 0.0;
        for (int k = 0; k < MAIN_THREADS / 32; k++) t += sh[k];
        g_part[blockIdx.x] = t;
    }
}

// ---------------- kernel: deterministic final reduce -------------------------
__global__ void k_final(float* __restrict__ out) {
    __shared__ double sh[256];
    double t = 0.0;
    for (int i = threadIdx.x; i < MAIN_BLOCKS; i += 256) t += g_part[i];
    sh[threadIdx.x] = t;
    __syncthreads();
    for (int s = 128; s; s >>= 1) {
        if (threadIdx.x < s) sh[threadIdx.x] += sh[threadIdx.x + s];
        __syncthreads();
    }
    if (threadIdx.x == 0) out[0] = (float)(-sh[0]);   // elbo = -sum(likelihood)
}

// ---------------- launch ------------------------------------------------------
extern "C" void kernel_launch(void* const* d_in, const int* in_sizes, int n_in,
                              void* d_out, int out_size) {
    const float* latent = (const float*)d_in[0];
    const float* coord  = (const float*)d_in[1];
    const int*   goi    = (const int*)  d_in[2];
    const int*   cxg    = (const int*)  d_in[3];   // cut_local_cellxgene_ix
    const int*   lcxg   = (const int*)  d_in[4];   // cut_localcellxgene_ix
    const int*   gloc   = (const int*)  d_in[5];   // cut_local_gene_ix
    const float* hw     = (const float*)d_in[6];   // height_slope_w
    const float* wo     = (const float*)d_in[7];   // overall_slope_w
    const float* ob     = (const float*)d_in[8];   // overall_baseline
    const float* sb     = (const float*)d_in[9];   // spline_baseline
    float* out = (float*)d_out;
    int ncuts = in_sizes[1];

    {
        dim3 grid((NGT + 255) / 256, (NC + 15) / 16);
        k_logits<<<grid, 256>>>(latent, wo, ob);
    }
    k_lse<<<NC, 512>>>();
    k_bexp<<<NGOI, 132>>>(sb, goi);
    k_e128<<<NGOI, 256>>>(latent, hw, goi);
    {
        dim3 grid(NGOI, CSPLIT);
        k_delta<<<grid, 256>>>(latent, hw, goi);
    }
    k_main<<<MAIN_BLOCKS, MAIN_THREADS>>>(coord, cxg, lcxg, gloc, ncuts);
    k_final<<<1, 256>>>(out);
}